// round 13
// baseline (speedup 1.0000x reference)
#include <cuda_runtime.h>
#include <cuda_fp16.h>
#include <cstdint>

#define N_NODES 50000
#define N_EDGES 800000
#define FEAT    1024
#define EMB     128
#define NPAD    50048          // padded rows for g_x16 (zero-init)

// ---------------------------------------------------------------------------
// Device-global scratch (no allocs allowed; __device__ globals are zero-init)
// ---------------------------------------------------------------------------
__device__ float  g_h[(size_t)N_NODES * EMB];     // h = x @ W^T   (25.6 MB)
__device__ __half g_x16[(size_t)NPAD * FEAT];     // x in fp16 (102.5 MB)
__device__ __half g_wh16[(size_t)EMB * FEAT];     // W split hi (fp16)
__device__ __half g_wl16[(size_t)EMB * FEAT];     // W split lo (fp16)
__device__ int    g_cnt[N_NODES];                 // degree counters
__device__ int    g_off[N_NODES + 1];             // CSR offsets
__device__ int2   g_edge[N_EDGES];                // bucketed (col, val-bits)

// ---------------------------------------------------------------------------
// helpers
// ---------------------------------------------------------------------------
__device__ __forceinline__ void split16(float v, __half& hi, __half& lo) {
    hi = __float2half_rn(v);
    lo = __float2half_rn(v - __half2float(hi));
}

__device__ __forceinline__ void mma16(float d[4], const uint32_t a[4],
                                      uint32_t b0, uint32_t b1) {
    asm volatile(
        "mma.sync.aligned.m16n8k16.row.col.f32.f16.f16.f32 "
        "{%0,%1,%2,%3}, {%4,%5,%6,%7}, {%8,%9}, {%0,%1,%2,%3};"
        : "+f"(d[0]), "+f"(d[1]), "+f"(d[2]), "+f"(d[3])
        : "r"(a[0]), "r"(a[1]), "r"(a[2]), "r"(a[3]), "r"(b0), "r"(b1));
}

#define CP_ASYNC16(dst, src) \
    asm volatile("cp.async.cg.shared.global [%0], [%1], 16;" \
        :: "r"(dst), "l"(src) : "memory")
#define CP_COMMIT() asm volatile("cp.async.commit_group;" ::: "memory")
#define CP_WAIT1()  asm volatile("cp.async.wait_group 1;" ::: "memory")

// ---------------------------------------------------------------------------
// split W once into fp16 hi/lo
// ---------------------------------------------------------------------------
__global__ void split_w_kernel(const float* __restrict__ w) {
    int i = blockIdx.x * blockDim.x + threadIdx.x;
    if (i < EMB * FEAT) {
        __half h, l;
        split16(w[i], h, l);
        g_wh16[i] = h;
        g_wl16[i] = l;
    }
}

// ---------------------------------------------------------------------------
// convert x -> fp16 once (8 elements per thread)
// ---------------------------------------------------------------------------
__global__ void conv_x_kernel(const float* __restrict__ x) {
    size_t i = ((size_t)blockIdx.x * blockDim.x + threadIdx.x) * 8;
    if (i < (size_t)N_NODES * FEAT) {
        float4 a = *(const float4*)(x + i);
        float4 b = *(const float4*)(x + i + 4);
        __half2 h[4];
        h[0] = __float22half2_rn(make_float2(a.x, a.y));
        h[1] = __float22half2_rn(make_float2(a.z, a.w));
        h[2] = __float22half2_rn(make_float2(b.x, b.y));
        h[3] = __float22half2_rn(make_float2(b.z, b.w));
        *(uint4*)(g_x16 + i) = *(const uint4*)h;
    }
}

// ---------------------------------------------------------------------------
// GEMM: h = x16 @ W^T via mma.sync fp16, 2-pass split (xh*wh + xh*wl).
// 3-stage cp.async pipeline: tiles stream gmem->smem with no register
// staging and ONE syncthreads per iteration; DRAM latency hidden 2 deep.
// CTA 128x128, KC=32, 8 warps (4M x 2N), warp tile 32x64, occ=2.
// ---------------------------------------------------------------------------
#define SH  40                         // half row stride (conflict-free LDS)
#define KC  32
#define NKIT (FEAT / KC)               // 32
#define TILE_HALVES (128 * SH)         // 5120 halves = 10240 B
#define TILEB  (TILE_HALVES * 2)       // 10240
#define STAGEB (3 * TILEB)             // 30720
#define NSTAGE 3
#define SMEMB  (NSTAGE * STAGEB)       // 92160

__global__ __launch_bounds__(256, 2)
void gemm_fp16_mma(void) {
    extern __shared__ __half dsm[];
    uint32_t sbase;
    asm("{ .reg .u64 t; cvta.to.shared.u64 t, %1; cvt.u32.u64 %0, t; }"
        : "=r"(sbase) : "l"(dsm));

    const int tid  = threadIdx.x;
    const int m0   = blockIdx.x * 128;
    const int wid  = tid >> 5;
    const int lane = tid & 31;
    const int wm   = (wid & 3) * 32;
    const int wn   = (wid >> 2) * 64;
    const int g    = lane >> 2;
    const int t    = lane & 3;

    // load mapping: 2 threads per row, 32 bytes each (2 x 16B cp.async)
    const int lrow = tid >> 1;
    const int lk   = (tid & 1) * 16;
    const __half* xrow  = g_x16  + (size_t)(m0 + lrow) * FEAT;  // padded: safe
    const __half* whrow = g_wh16 + (size_t)lrow * FEAT;
    const __half* wlrow = g_wl16 + (size_t)lrow * FEAT;
    const uint32_t doff = (uint32_t)(lrow * SH + lk) * 2;       // bytes in tile

    float acc[2][8][4];
#pragma unroll
    for (int mi = 0; mi < 2; mi++)
#pragma unroll
        for (int ni = 0; ni < 8; ni++)
#pragma unroll
            for (int j = 0; j < 4; j++) acc[mi][ni][j] = 0.f;

    // ---- prologue: issue stages 0 and 1 ----
#pragma unroll
    for (int s = 0; s < 2; s++) {
        const int k0 = s * KC;
        const uint32_t sb = sbase + s * STAGEB;
        CP_ASYNC16(sb + doff,               xrow + k0 + lk);
        CP_ASYNC16(sb + doff + 16,          xrow + k0 + lk + 8);
        CP_ASYNC16(sb + TILEB + doff,       whrow + k0 + lk);
        CP_ASYNC16(sb + TILEB + doff + 16,  whrow + k0 + lk + 8);
        CP_ASYNC16(sb + 2*TILEB + doff,     wlrow + k0 + lk);
        CP_ASYNC16(sb + 2*TILEB + doff + 16, wlrow + k0 + lk + 8);
        CP_COMMIT();
    }

    for (int it = 0; it < NKIT; ++it) {
        CP_WAIT1();            // stage it complete (<=1 newer group pending)
        __syncthreads();       // cross-thread visibility + safe overwrite

        // issue stage it+2 into buffer (it+2)%3 (consumed at iter it-1)
        if (it + 2 < NKIT) {
            const int k0 = (it + 2) * KC;
            const uint32_t sb = sbase + ((it + 2) % NSTAGE) * STAGEB;
            CP_ASYNC16(sb + doff,               xrow + k0 + lk);
            CP_ASYNC16(sb + doff + 16,          xrow + k0 + lk + 8);
            CP_ASYNC16(sb + TILEB + doff,       whrow + k0 + lk);
            CP_ASYNC16(sb + TILEB + doff + 16,  whrow + k0 + lk + 8);
            CP_ASYNC16(sb + 2*TILEB + doff,     wlrow + k0 + lk);
            CP_ASYNC16(sb + 2*TILEB + doff + 16, wlrow + k0 + lk + 8);
            CP_COMMIT();
        } else {
            CP_COMMIT();       // keep group count advancing for wait_group 1
        }

        // ---- MMAs on stage it%3 (proven scalar-LDS pattern) ----
        const __half* axh = dsm + (it % NSTAGE) * (STAGEB / 2);
        const __half* swh = axh + TILE_HALVES;
        const __half* swl = axh + 2 * TILE_HALVES;
#pragma unroll
        for (int ks = 0; ks < 2; ks++) {
            const int k0 = ks * 16;
            uint32_t ah[2][4];
#pragma unroll
            for (int mi = 0; mi < 2; mi++) {
                const int r = wm + mi * 16;
                const __half* bh = axh + k0 + 2 * t;
                ah[mi][0] = *(const uint32_t*)(bh + (r + g)     * SH);
                ah[mi][1] = *(const uint32_t*)(bh + (r + g + 8) * SH);
                ah[mi][2] = *(const uint32_t*)(bh + (r + g)     * SH + 8);
                ah[mi][3] = *(const uint32_t*)(bh + (r + g + 8) * SH + 8);
            }
#pragma unroll
            for (int ni = 0; ni < 8; ni++) {
                const int n = wn + ni * 8 + g;
                uint32_t bh0 = *(const uint32_t*)(swh + n * SH + k0 + 2 * t);
                uint32_t bh1 = *(const uint32_t*)(swh + n * SH + k0 + 2 * t + 8);
                uint32_t bl0 = *(const uint32_t*)(swl + n * SH + k0 + 2 * t);
                uint32_t bl1 = *(const uint32_t*)(swl + n * SH + k0 + 2 * t + 8);
#pragma unroll
                for (int mi = 0; mi < 2; mi++) {
                    mma16(acc[mi][ni], ah[mi], bh0, bh1);   // xh*wh
                    mma16(acc[mi][ni], ah[mi], bl0, bl1);   // xh*wl
                }
            }
        }
    }

    // epilogue
#pragma unroll
    for (int mi = 0; mi < 2; mi++) {
#pragma unroll
        for (int ni = 0; ni < 8; ni++) {
            const int r = m0 + wm + mi * 16 + g;
            const int c = wn + ni * 8 + 2 * t;
            if (r < N_NODES)
                *(float2*)(g_h + (size_t)r * EMB + c) =
                    make_float2(acc[mi][ni][0], acc[mi][ni][1]);
            if (r + 8 < N_NODES)
                *(float2*)(g_h + (size_t)(r + 8) * EMB + c) =
                    make_float2(acc[mi][ni][2], acc[mi][ni][3]);
        }
    }
}

// ---------------------------------------------------------------------------
// CSR build: memset(g_cnt) -> hist -> fused scan -> bucket
// ---------------------------------------------------------------------------
__global__ void hist_kernel(const int* __restrict__ row) {
    int e = blockIdx.x * blockDim.x + threadIdx.x;
    if (e < N_EDGES) atomicAdd(&g_cnt[row[e]], 1);
}

#define SCAN_T 1024
#define SCAN_CHUNK ((N_NODES + SCAN_T - 1) / SCAN_T)   // 49

__global__ __launch_bounds__(SCAN_T)
void scan_fused_kernel() {
    __shared__ int s[SCAN_T];
    const int tid = threadIdx.x;
    const int beg = tid * SCAN_CHUNK;
    const int end = min(beg + SCAN_CHUNK, N_NODES);

    int sum = 0;
    for (int i = beg; i < end; i++) sum += g_cnt[i];
    s[tid] = sum;
    __syncthreads();
#pragma unroll
    for (int d = 1; d < SCAN_T; d <<= 1) {
        int tmp = (tid >= d) ? s[tid - d] : 0;
        __syncthreads();
        s[tid] += tmp;
        __syncthreads();
    }
    int run = s[tid] - sum;
    for (int i = beg; i < end; i++) {
        int c = g_cnt[i];
        g_off[i] = run;
        run += c;
        g_cnt[i] = 0;
    }
    if (tid == 0) g_off[N_NODES] = N_EDGES;
}

__global__ void bucket_kernel(const int* __restrict__ row,
                              const int* __restrict__ col,
                              const float* __restrict__ vals) {
    int e = blockIdx.x * blockDim.x + threadIdx.x;
    if (e < N_EDGES) {
        int r = row[e];
        int pos = g_off[r] + atomicAdd(&g_cnt[r], 1);
        g_edge[pos] = make_int2(col[e], __float_as_int(vals[e]));
    }
}

// ---------------------------------------------------------------------------
// Gather: one warp per destination node; atomic-free, writes out once.
// ---------------------------------------------------------------------------
__global__ void gather_kernel(float* __restrict__ out) {
    const int lane = threadIdx.x & 31;
    const int node = (blockIdx.x * blockDim.x + threadIdx.x) >> 5;
    if (node >= N_NODES) return;

    const int beg = g_off[node];
    const int end = g_off[node + 1];

    float4 acc = make_float4(0.f, 0.f, 0.f, 0.f);
    for (int e = beg; e < end; e++) {
        const int2 ev = g_edge[e];
        const float v = __int_as_float(ev.y);
        const float4 hv = __ldg((const float4*)(g_h + (size_t)ev.x * EMB) + lane);
        acc.x = fmaf(v, hv.x, acc.x);
        acc.y = fmaf(v, hv.y, acc.y);
        acc.z = fmaf(v, hv.z, acc.z);
        acc.w = fmaf(v, hv.w, acc.w);
    }
    *((float4*)(out + (size_t)node * EMB) + lane) = acc;
}

// ---------------------------------------------------------------------------
// Launch. Host order keeps GEMM as launch #6 for ncu (-s 5 -c 1):
//   split_w(1), conv_x(2), memset(3), hist(4), scan(5), GEMM(6), bucket, gather
// ---------------------------------------------------------------------------
extern "C" void kernel_launch(void* const* d_in, const int* in_sizes, int n_in,
                              void* d_out, int out_size) {
    const float* x    = (const float*)d_in[0];
    const float* w    = (const float*)d_in[1];
    const int*   row  = (const int*)  d_in[2];
    const int*   col  = (const int*)  d_in[3];
    const float* vals = (const float*)d_in[4];
    float*       out  = (float*)d_out;

    static cudaStream_t s_side = nullptr;
    static cudaEvent_t  ev_fork = nullptr, ev_join = nullptr;
    static bool attr_set = false;
    if (s_side == nullptr) {
        cudaStreamCreateWithFlags(&s_side, cudaStreamNonBlocking);
        cudaEventCreateWithFlags(&ev_fork, cudaEventDisableTiming);
        cudaEventCreateWithFlags(&ev_join, cudaEventDisableTiming);
    }
    if (!attr_set) {
        cudaFuncSetAttribute(gemm_fp16_mma,
                             cudaFuncAttributeMaxDynamicSharedMemorySize, SMEMB);
        attr_set = true;
    }

    int* cnt_ptr = nullptr;
    cudaGetSymbolAddress((void**)&cnt_ptr, g_cnt);

    // (1) main: split W
    split_w_kernel<<<(EMB * FEAT + 255) / 256, 256>>>(w);
    // (2) main: convert x -> fp16
    conv_x_kernel<<<(N_NODES * FEAT / 8 + 255) / 256, 256>>>(x);

    // fork side stream (CSR build overlaps conv_x tail + GEMM)
    cudaEventRecord(ev_fork, 0);
    cudaStreamWaitEvent(s_side, ev_fork, 0);

    // (3-5) side: CSR build
    cudaMemsetAsync(cnt_ptr, 0, N_NODES * sizeof(int), s_side);
    hist_kernel<<<(N_EDGES + 255) / 256, 256, 0, s_side>>>(row);
    scan_fused_kernel<<<1, SCAN_T, 0, s_side>>>();

    // (6) main: GEMM  <-- ncu window
    gemm_fp16_mma<<<(N_NODES + 127) / 128, 256, SMEMB>>>();

    // (7) side: bucket
    bucket_kernel<<<(N_EDGES + 255) / 256, 256, 0, s_side>>>(row, col, vals);
    cudaEventRecord(ev_join, s_side);

    // (8) join, then gather
    cudaStreamWaitEvent(0, ev_join, 0);
    gather_kernel<<<(N_NODES * 32 + 255) / 256, 256>>>(out);
}